// round 10
// baseline (speedup 1.0000x reference)
#include <cuda_runtime.h>
#include <cuda_bf16.h>
#include <cstddef>

#define N_NODES 50000
#define N_EDGES 800000
#define D_IN    128
#define D_HID   256
#define D_OUT   128

// ---------------- device scratch (static, allocation-free) ----------------
// Only ever referenced from DEVICE code (never from host).
__device__ int   g_is64;                       // 1 if edge_index is int64, 0 if int32
__device__ int   g_cnt[N_NODES];
__device__ int   g_rowstart[N_NODES + 1];
__device__ int   g_work[N_NODES];
__device__ int   g_csr_src[N_EDGES];
__device__ float g_z[(size_t)N_NODES * D_IN];  // layer1 agg; reused as z = h@W2_l
__device__ float g_h[(size_t)N_NODES * D_HID];

// ---------------- edge_index dtype detection ----------------
// int64 little-endian values < 2^31 have every odd 32-bit word == 0.
__global__ void detect_k(const int* __restrict__ ei32) {
    if (threadIdx.x == 0 && blockIdx.x == 0) {
        int is64 = 1;
        #pragma unroll
        for (int i = 1; i < 64; i += 2)
            if (ei32[i] != 0) is64 = 0;
        g_is64 = is64;
    }
}

__device__ __forceinline__ int load_edge(const void* ei, size_t idx, int is64) {
    if (is64) return (int)((const long long*)ei)[idx];
    return ((const int*)ei)[idx];
}

// ---------------- CSR build ----------------
__global__ void zero_cnt_k() {
    int i = blockIdx.x * blockDim.x + threadIdx.x;
    if (i < N_NODES) g_cnt[i] = 0;
}

__global__ void count_k(const void* __restrict__ ei) {
    int i = blockIdx.x * blockDim.x + threadIdx.x;
    if (i < N_EDGES) {
        int is64 = g_is64;
        int d = load_edge(ei, (size_t)N_EDGES + i, is64);   // dst row
        if ((unsigned)d < (unsigned)N_NODES) atomicAdd(&g_cnt[d], 1);
    }
}

// ---------------- fast single-block scan: 1024 threads x 49 items ----------------
// phase 1: per-thread sequential sum; phase 2: warp-shuffle block scan of 1024
// partials (2 barriers); phase 3: per-thread sequential exclusive write-back.
__global__ __launch_bounds__(1024) void scan_k() {
    const int ITEMS = 49;                       // 1024*49 = 50176 >= 50000
    __shared__ int warp_sums[32];
    int t = threadIdx.x;
    int lane = t & 31, wid = t >> 5;
    int base = t * ITEMS;

    int sum = 0;
    #pragma unroll
    for (int j = 0; j < ITEMS; j++) {
        int i = base + j;
        if (i < N_NODES) sum += g_cnt[i];
    }

    // warp inclusive scan of thread sums
    int v = sum;
    #pragma unroll
    for (int off = 1; off < 32; off <<= 1) {
        int u = __shfl_up_sync(0xffffffffu, v, off);
        if (lane >= off) v += u;
    }
    if (lane == 31) warp_sums[wid] = v;
    __syncthreads();
    if (wid == 0) {
        int w = warp_sums[lane];
        #pragma unroll
        for (int off = 1; off < 32; off <<= 1) {
            int u = __shfl_up_sync(0xffffffffu, w, off);
            if (lane >= off) w += u;
        }
        warp_sums[lane] = w;
    }
    __syncthreads();

    // exclusive prefix for this thread's chunk
    int excl = v - sum + (wid > 0 ? warp_sums[wid - 1] : 0);

    int run = excl;
    #pragma unroll
    for (int j = 0; j < ITEMS; j++) {
        int i = base + j;
        if (i < N_NODES) {
            g_rowstart[i] = run;
            g_work[i]     = run;
            run += g_cnt[i];
        }
    }
    if (t == 1023) g_rowstart[N_NODES] = run;   // run == total (this thread's items all OOB)
}

__global__ void place_k(const void* __restrict__ ei) {
    int i = blockIdx.x * blockDim.x + threadIdx.x;
    if (i < N_EDGES) {
        int is64 = g_is64;
        int s = load_edge(ei, (size_t)i, is64);              // src row
        int d = load_edge(ei, (size_t)N_EDGES + i, is64);    // dst row
        if ((unsigned)d < (unsigned)N_NODES && (unsigned)s < (unsigned)N_NODES) {
            int pos = atomicAdd(&g_work[d], 1);
            g_csr_src[pos] = s;
        }
    }
}

// ---------------- gather-mean body: one warp per destination node (F=128) ----------------
template <int ADD>
__device__ __forceinline__ void gather128_body(const float* __restrict__ feat,
                                               float* __restrict__ agg) {
    int warp = (blockIdx.x * blockDim.x + threadIdx.x) >> 5;
    int lane = threadIdx.x & 31;
    if (warp >= N_NODES) return;
    int beg = g_rowstart[warp], end = g_rowstart[warp + 1];
    float4 acc = make_float4(0.f, 0.f, 0.f, 0.f);
    for (int e = beg; e < end; e++) {
        int s = g_csr_src[e];
        float4 v = ((const float4*)(feat + (size_t)s * 128))[lane];
        acc.x += v.x; acc.y += v.y; acc.z += v.z; acc.w += v.w;
    }
    int deg = end - beg;
    float scale = 1.0f / (float)(deg > 0 ? deg : 1);
    float4* o = (float4*)(agg + (size_t)warp * 128);
    float4 r;
    if (ADD) {
        float4 prev = o[lane];
        r.x = prev.x + acc.x * scale; r.y = prev.y + acc.y * scale;
        r.z = prev.z + acc.z * scale; r.w = prev.w + acc.w * scale;
    } else {
        r.x = acc.x * scale; r.y = acc.y * scale;
        r.z = acc.z * scale; r.w = acc.w * scale;
    }
    o[lane] = r;
}

__global__ void gather_x_to_z_k(const float* __restrict__ x) {
    gather128_body<0>(x, g_z);
}
__global__ void gather_z_add_out_k(float* __restrict__ out) {
    gather128_body<1>(g_z, out);
}

// ---------------- fused dual GEMM body: Out = A@Wl + X@Wr + bias (+relu) ----------------
// A, X: [N, K] row-major;  Wl, Wr: [K, M] row-major;  Out: [N, M]
// 128x64 output tile per 256-thread block, BK=16, 8x4 microtile per thread (dual).
__device__ __forceinline__ void sage_gemm_body(
    const float* __restrict__ A, const float* __restrict__ X,
    const float* __restrict__ Wl, const float* __restrict__ Wr,
    const float* __restrict__ bias, float* __restrict__ Out,
    int N, int K, int M, int relu)
{
    __shared__ float sAa[16][128];
    __shared__ float sAx[16][128];
    __shared__ float sWl[16][64];
    __shared__ float sWr[16][64];

    const int tid = threadIdx.x;
    const int tx = tid & 15;
    const int ty = tid >> 4;
    const int tx4 = tx * 4, ty8 = ty * 8;
    const int row0 = blockIdx.y * 128;
    const int col0 = blockIdx.x * 64;

    const int ar = tid >> 1;           // 0..127 : tile row
    const int ak = (tid & 1) * 8;      // 0 or 8 : k offset
    const int wk = tid >> 4;           // 0..15 : W tile k
    const int wc = (tid & 15) * 4;     // 0..60 : W tile col

    const int arow = row0 + ar;
    const bool arow_ok = (arow < N);

    float acc[8][4];
    #pragma unroll
    for (int i = 0; i < 8; i++)
        #pragma unroll
        for (int j = 0; j < 4; j++) acc[i][j] = 0.f;

    for (int k0 = 0; k0 < K; k0 += 16) {
        float4 va0 = make_float4(0.f, 0.f, 0.f, 0.f), va1 = va0;
        float4 vx0 = va0, vx1 = va0;
        if (arow_ok) {
            const float* ap = A + (size_t)arow * K + k0 + ak;
            const float* xp = X + (size_t)arow * K + k0 + ak;
            va0 = *(const float4*)(ap);
            va1 = *(const float4*)(ap + 4);
            vx0 = *(const float4*)(xp);
            vx1 = *(const float4*)(xp + 4);
        }
        sAa[ak + 0][ar] = va0.x; sAa[ak + 1][ar] = va0.y;
        sAa[ak + 2][ar] = va0.z; sAa[ak + 3][ar] = va0.w;
        sAa[ak + 4][ar] = va1.x; sAa[ak + 5][ar] = va1.y;
        sAa[ak + 6][ar] = va1.z; sAa[ak + 7][ar] = va1.w;
        sAx[ak + 0][ar] = vx0.x; sAx[ak + 1][ar] = vx0.y;
        sAx[ak + 2][ar] = vx0.z; sAx[ak + 3][ar] = vx0.w;
        sAx[ak + 4][ar] = vx1.x; sAx[ak + 5][ar] = vx1.y;
        sAx[ak + 6][ar] = vx1.z; sAx[ak + 7][ar] = vx1.w;

        *(float4*)&sWl[wk][wc] = *(const float4*)(Wl + (size_t)(k0 + wk) * M + col0 + wc);
        *(float4*)&sWr[wk][wc] = *(const float4*)(Wr + (size_t)(k0 + wk) * M + col0 + wc);

        __syncthreads();

        #pragma unroll
        for (int k = 0; k < 16; k++) {
            float4 a0 = *(const float4*)&sAa[k][ty8];
            float4 a1 = *(const float4*)&sAa[k][ty8 + 4];
            float4 x0 = *(const float4*)&sAx[k][ty8];
            float4 x1 = *(const float4*)&sAx[k][ty8 + 4];
            float4 bl = *(const float4*)&sWl[k][tx4];
            float4 br = *(const float4*)&sWr[k][tx4];
            float a_[8] = {a0.x, a0.y, a0.z, a0.w, a1.x, a1.y, a1.z, a1.w};
            float x_[8] = {x0.x, x0.y, x0.z, x0.w, x1.x, x1.y, x1.z, x1.w};
            float l_[4] = {bl.x, bl.y, bl.z, bl.w};
            float r_[4] = {br.x, br.y, br.z, br.w};
            #pragma unroll
            for (int i = 0; i < 8; i++)
                #pragma unroll
                for (int j = 0; j < 4; j++)
                    acc[i][j] += a_[i] * l_[j] + x_[i] * r_[j];
        }
        __syncthreads();
    }

    #pragma unroll
    for (int i = 0; i < 8; i++) {
        int r = row0 + ty8 + i;
        if (r < N) {
            float4 o;
            o.x = acc[i][0] + bias[col0 + tx4 + 0];
            o.y = acc[i][1] + bias[col0 + tx4 + 1];
            o.z = acc[i][2] + bias[col0 + tx4 + 2];
            o.w = acc[i][3] + bias[col0 + tx4 + 3];
            if (relu) {
                o.x = fmaxf(o.x, 0.f); o.y = fmaxf(o.y, 0.f);
                o.z = fmaxf(o.z, 0.f); o.w = fmaxf(o.w, 0.f);
            }
            *(float4*)(Out + (size_t)r * M + col0 + tx4) = o;
        }
    }
}

// ---------------- single GEMM body: Out = A@W (+ optional bias) ----------------
__device__ __forceinline__ void gemm_single_body(
    const float* __restrict__ A, const float* __restrict__ W,
    const float* __restrict__ bias, float* __restrict__ Out,
    int N, int K, int M)
{
    __shared__ float sA[16][128];
    __shared__ float sW[16][64];

    const int tid = threadIdx.x;
    const int tx = tid & 15;
    const int ty = tid >> 4;
    const int tx4 = tx * 4, ty8 = ty * 8;
    const int row0 = blockIdx.y * 128;
    const int col0 = blockIdx.x * 64;

    const int ar = tid >> 1;
    const int ak = (tid & 1) * 8;
    const int wk = tid >> 4;
    const int wc = (tid & 15) * 4;

    const int arow = row0 + ar;
    const bool arow_ok = (arow < N);

    float acc[8][4];
    #pragma unroll
    for (int i = 0; i < 8; i++)
        #pragma unroll
        for (int j = 0; j < 4; j++) acc[i][j] = 0.f;

    for (int k0 = 0; k0 < K; k0 += 16) {
        float4 va0 = make_float4(0.f, 0.f, 0.f, 0.f), va1 = va0;
        if (arow_ok) {
            const float* ap = A + (size_t)arow * K + k0 + ak;
            va0 = *(const float4*)(ap);
            va1 = *(const float4*)(ap + 4);
        }
        sA[ak + 0][ar] = va0.x; sA[ak + 1][ar] = va0.y;
        sA[ak + 2][ar] = va0.z; sA[ak + 3][ar] = va0.w;
        sA[ak + 4][ar] = va1.x; sA[ak + 5][ar] = va1.y;
        sA[ak + 6][ar] = va1.z; sA[ak + 7][ar] = va1.w;

        *(float4*)&sW[wk][wc] = *(const float4*)(W + (size_t)(k0 + wk) * M + col0 + wc);

        __syncthreads();

        #pragma unroll
        for (int k = 0; k < 16; k++) {
            float4 a0 = *(const float4*)&sA[k][ty8];
            float4 a1 = *(const float4*)&sA[k][ty8 + 4];
            float4 wv = *(const float4*)&sW[k][tx4];
            float a_[8] = {a0.x, a0.y, a0.z, a0.w, a1.x, a1.y, a1.z, a1.w};
            float w_[4] = {wv.x, wv.y, wv.z, wv.w};
            #pragma unroll
            for (int i = 0; i < 8; i++)
                #pragma unroll
                for (int j = 0; j < 4; j++)
                    acc[i][j] += a_[i] * w_[j];
        }
        __syncthreads();
    }

    #pragma unroll
    for (int i = 0; i < 8; i++) {
        int r = row0 + ty8 + i;
        if (r < N) {
            float4 o;
            float bx = bias ? bias[col0 + tx4 + 0] : 0.f;
            float by = bias ? bias[col0 + tx4 + 1] : 0.f;
            float bz = bias ? bias[col0 + tx4 + 2] : 0.f;
            float bw = bias ? bias[col0 + tx4 + 3] : 0.f;
            o.x = acc[i][0] + bx; o.y = acc[i][1] + by;
            o.z = acc[i][2] + bz; o.w = acc[i][3] + bw;
            *(float4*)(Out + (size_t)r * M + col0 + tx4) = o;
        }
    }
}

// ---------------- GEMM wrappers binding scratch symbols (device side) ----------------
__global__ __launch_bounds__(256) void gemm_l1_k(
    const float* __restrict__ x, const float* __restrict__ W1l,
    const float* __restrict__ W1r, const float* __restrict__ b1)
{
    sage_gemm_body(g_z, x, W1l, W1r, b1, g_h, N_NODES, D_IN, D_HID, 1);
}

__global__ __launch_bounds__(256) void gemm_l2z_k(const float* __restrict__ W2l)
{
    gemm_single_body(g_h, W2l, nullptr, g_z, N_NODES, D_HID, D_OUT);
}

__global__ __launch_bounds__(256) void gemm_l2o_k(
    const float* __restrict__ W2r, const float* __restrict__ b2,
    float* __restrict__ out)
{
    gemm_single_body(g_h, W2r, b2, out, N_NODES, D_HID, D_OUT);
}

// ---------------- launch ----------------
extern "C" void kernel_launch(void* const* d_in, const int* in_sizes, int n_in,
                              void* d_out, int out_size) {
    const float* x   = (const float*)d_in[0];
    const void*  ei  = d_in[1];                 // int32 or int64; detected at runtime
    const float* W1l = (const float*)d_in[2];
    const float* b1  = (const float*)d_in[3];
    const float* W1r = (const float*)d_in[4];
    const float* W2l = (const float*)d_in[5];
    const float* b2  = (const float*)d_in[6];
    const float* W2r = (const float*)d_in[7];
    float*       out = (float*)d_out;

    // CSR build (per launch; deterministic)
    detect_k<<<1, 32>>>((const int*)ei);
    zero_cnt_k<<<(N_NODES + 255) / 256, 256>>>();
    count_k<<<(N_EDGES + 255) / 256, 256>>>(ei);
    scan_k<<<1, 1024>>>();
    place_k<<<(N_EDGES + 255) / 256, 256>>>(ei);

    const int gather_blocks = (N_NODES * 32 + 255) / 256;
    const dim3 g1(D_HID / 64, (N_NODES + 127) / 128);
    const dim3 g2(D_OUT / 64, (N_NODES + 127) / 128);

    // Layer 1: g_z = mean_agg(x) ; g_h = relu(g_z@W1_l + x@W1_r + b1)
    gather_x_to_z_k<<<gather_blocks, 256>>>(x);
    gemm_l1_k<<<g1, 256>>>(x, W1l, W1r, b1);

    // Layer 2 (mean-linearity reorder):
    //   g_z = g_h@W2_l ; out = g_h@W2_r + b2 ; out += mean_agg(g_z)
    gemm_l2z_k<<<g2, 256>>>(W2l);
    gemm_l2o_k<<<g2, 256>>>(W2r, b2, out);
    gather_z_add_out_k<<<gather_blocks, 256>>>(out);
}

// round 11
// speedup vs baseline: 1.1017x; 1.1017x over previous
#include <cuda_runtime.h>
#include <cuda_bf16.h>
#include <cstddef>

#define N_NODES 50000
#define N_EDGES 800000
#define D_IN    128
#define D_HID   256
#define D_OUT   128
#define NBLK    49          // ceil(N_NODES / 1024)

// ---------------- device scratch (static, allocation-free) ----------------
// Only ever referenced from DEVICE code (never from host).
__device__ int   g_is64;                       // 1 if edge_index is int64, 0 if int32
__device__ int   g_cnt[N_NODES];
__device__ int   g_rowstart[N_NODES + 1];
__device__ int   g_work[N_NODES];
__device__ int   g_csr_src[N_EDGES];
__device__ int   g_blocksum[NBLK];
__device__ int   g_blockoff[NBLK + 1];
__device__ float g_z[(size_t)N_NODES * D_IN];  // layer1 agg; reused as z = h@W2_l
__device__ float g_h[(size_t)N_NODES * D_HID];

// ---------------- edge_index dtype detection ----------------
// int64 little-endian values < 2^31 have every odd 32-bit word == 0.
__global__ void detect_k(const int* __restrict__ ei32) {
    if (threadIdx.x == 0 && blockIdx.x == 0) {
        int is64 = 1;
        #pragma unroll
        for (int i = 1; i < 64; i += 2)
            if (ei32[i] != 0) is64 = 0;
        g_is64 = is64;
    }
}

__device__ __forceinline__ int load_edge(const void* ei, size_t idx, int is64) {
    if (is64) return (int)((const long long*)ei)[idx];
    return ((const int*)ei)[idx];
}

// ---------------- CSR build ----------------
__global__ void zero_cnt_k() {
    int i = blockIdx.x * blockDim.x + threadIdx.x;
    if (i < N_NODES) g_cnt[i] = 0;
}

__global__ void count_k(const void* __restrict__ ei) {
    int i = blockIdx.x * blockDim.x + threadIdx.x;
    if (i < N_EDGES) {
        int is64 = g_is64;
        int d = load_edge(ei, (size_t)N_EDGES + i, is64);   // dst row
        if ((unsigned)d < (unsigned)N_NODES) atomicAdd(&g_cnt[d], 1);
    }
}

// ---------------- three-kernel coalesced scan ----------------
// pass A: per-block reduction of 1024-wide tiles (coalesced)
__global__ __launch_bounds__(1024) void scan_a_k() {
    __shared__ int wsum[32];
    int t = threadIdx.x, lane = t & 31, wid = t >> 5;
    int i = blockIdx.x * 1024 + t;
    int v = (i < N_NODES) ? g_cnt[i] : 0;
    #pragma unroll
    for (int off = 16; off > 0; off >>= 1)
        v += __shfl_down_sync(0xffffffffu, v, off);
    if (lane == 0) wsum[wid] = v;
    __syncthreads();
    if (wid == 0) {
        int w = wsum[lane];
        #pragma unroll
        for (int off = 16; off > 0; off >>= 1)
            w += __shfl_down_sync(0xffffffffu, w, off);
        if (lane == 0) g_blocksum[blockIdx.x] = w;
    }
}

// pass B: exclusive scan of NBLK block sums (single thread, unrolled indep loads)
__global__ void scan_b_k() {
    if (threadIdx.x == 0 && blockIdx.x == 0) {
        int run = 0;
        #pragma unroll
        for (int b = 0; b < NBLK; b++) {
            int s = g_blocksum[b];
            g_blockoff[b] = run;
            run += s;
        }
        g_blockoff[NBLK] = run;
        g_rowstart[N_NODES] = run;
    }
}

// pass C: per-block exclusive scan of its tile + block offset (coalesced, 2 barriers)
__global__ __launch_bounds__(1024) void scan_c_k() {
    __shared__ int wsum[32];
    int t = threadIdx.x, lane = t & 31, wid = t >> 5;
    int i = blockIdx.x * 1024 + t;
    int v = (i < N_NODES) ? g_cnt[i] : 0;

    // warp inclusive scan
    int inc = v;
    #pragma unroll
    for (int off = 1; off < 32; off <<= 1) {
        int u = __shfl_up_sync(0xffffffffu, inc, off);
        if (lane >= off) inc += u;
    }
    if (lane == 31) wsum[wid] = inc;
    __syncthreads();
    if (wid == 0) {
        int w = wsum[lane];
        #pragma unroll
        for (int off = 1; off < 32; off <<= 1) {
            int u = __shfl_up_sync(0xffffffffu, w, off);
            if (lane >= off) w += u;
        }
        wsum[lane] = w;
    }
    __syncthreads();

    int excl = inc - v + (wid > 0 ? wsum[wid - 1] : 0) + g_blockoff[blockIdx.x];
    if (i < N_NODES) {
        g_rowstart[i] = excl;
        g_work[i]     = excl;
    }
}

__global__ void place_k(const void* __restrict__ ei) {
    int i = blockIdx.x * blockDim.x + threadIdx.x;
    if (i < N_EDGES) {
        int is64 = g_is64;
        int s = load_edge(ei, (size_t)i, is64);              // src row
        int d = load_edge(ei, (size_t)N_EDGES + i, is64);    // dst row
        if ((unsigned)d < (unsigned)N_NODES && (unsigned)s < (unsigned)N_NODES) {
            int pos = atomicAdd(&g_work[d], 1);
            g_csr_src[pos] = s;
        }
    }
}

// ---------------- gather-mean body: one warp per destination node (F=128) ----------------
template <int ADD>
__device__ __forceinline__ void gather128_body(const float* __restrict__ feat,
                                               float* __restrict__ agg) {
    int warp = (blockIdx.x * blockDim.x + threadIdx.x) >> 5;
    int lane = threadIdx.x & 31;
    if (warp >= N_NODES) return;
    int beg = g_rowstart[warp], end = g_rowstart[warp + 1];
    float4 acc = make_float4(0.f, 0.f, 0.f, 0.f);
    for (int e = beg; e < end; e++) {
        int s = g_csr_src[e];
        float4 v = ((const float4*)(feat + (size_t)s * 128))[lane];
        acc.x += v.x; acc.y += v.y; acc.z += v.z; acc.w += v.w;
    }
    int deg = end - beg;
    float scale = 1.0f / (float)(deg > 0 ? deg : 1);
    float4* o = (float4*)(agg + (size_t)warp * 128);
    float4 r;
    if (ADD) {
        float4 prev = o[lane];
        r.x = prev.x + acc.x * scale; r.y = prev.y + acc.y * scale;
        r.z = prev.z + acc.z * scale; r.w = prev.w + acc.w * scale;
    } else {
        r.x = acc.x * scale; r.y = acc.y * scale;
        r.z = acc.z * scale; r.w = acc.w * scale;
    }
    o[lane] = r;
}

__global__ void gather_x_to_z_k(const float* __restrict__ x) {
    gather128_body<0>(x, g_z);
}
__global__ void gather_z_add_out_k(float* __restrict__ out) {
    gather128_body<1>(g_z, out);
}

// ---------------- fused dual GEMM body: Out = A@Wl + X@Wr + bias (+relu) ----------------
// A, X: [N, K] row-major;  Wl, Wr: [K, M] row-major;  Out: [N, M]
// 128x64 output tile per 256-thread block, BK=16, 8x4 microtile per thread (dual).
__device__ __forceinline__ void sage_gemm_body(
    const float* __restrict__ A, const float* __restrict__ X,
    const float* __restrict__ Wl, const float* __restrict__ Wr,
    const float* __restrict__ bias, float* __restrict__ Out,
    int N, int K, int M, int relu)
{
    __shared__ float sAa[16][128];
    __shared__ float sAx[16][128];
    __shared__ float sWl[16][64];
    __shared__ float sWr[16][64];

    const int tid = threadIdx.x;
    const int tx = tid & 15;
    const int ty = tid >> 4;
    const int tx4 = tx * 4, ty8 = ty * 8;
    const int row0 = blockIdx.y * 128;
    const int col0 = blockIdx.x * 64;

    const int ar = tid >> 1;           // 0..127 : tile row
    const int ak = (tid & 1) * 8;      // 0 or 8 : k offset
    const int wk = tid >> 4;           // 0..15 : W tile k
    const int wc = (tid & 15) * 4;     // 0..60 : W tile col

    const int arow = row0 + ar;
    const bool arow_ok = (arow < N);

    float acc[8][4];
    #pragma unroll
    for (int i = 0; i < 8; i++)
        #pragma unroll
        for (int j = 0; j < 4; j++) acc[i][j] = 0.f;

    for (int k0 = 0; k0 < K; k0 += 16) {
        float4 va0 = make_float4(0.f, 0.f, 0.f, 0.f), va1 = va0;
        float4 vx0 = va0, vx1 = va0;
        if (arow_ok) {
            const float* ap = A + (size_t)arow * K + k0 + ak;
            const float* xp = X + (size_t)arow * K + k0 + ak;
            va0 = *(const float4*)(ap);
            va1 = *(const float4*)(ap + 4);
            vx0 = *(const float4*)(xp);
            vx1 = *(const float4*)(xp + 4);
        }
        sAa[ak + 0][ar] = va0.x; sAa[ak + 1][ar] = va0.y;
        sAa[ak + 2][ar] = va0.z; sAa[ak + 3][ar] = va0.w;
        sAa[ak + 4][ar] = va1.x; sAa[ak + 5][ar] = va1.y;
        sAa[ak + 6][ar] = va1.z; sAa[ak + 7][ar] = va1.w;
        sAx[ak + 0][ar] = vx0.x; sAx[ak + 1][ar] = vx0.y;
        sAx[ak + 2][ar] = vx0.z; sAx[ak + 3][ar] = vx0.w;
        sAx[ak + 4][ar] = vx1.x; sAx[ak + 5][ar] = vx1.y;
        sAx[ak + 6][ar] = vx1.z; sAx[ak + 7][ar] = vx1.w;

        *(float4*)&sWl[wk][wc] = *(const float4*)(Wl + (size_t)(k0 + wk) * M + col0 + wc);
        *(float4*)&sWr[wk][wc] = *(const float4*)(Wr + (size_t)(k0 + wk) * M + col0 + wc);

        __syncthreads();

        #pragma unroll
        for (int k = 0; k < 16; k++) {
            float4 a0 = *(const float4*)&sAa[k][ty8];
            float4 a1 = *(const float4*)&sAa[k][ty8 + 4];
            float4 x0 = *(const float4*)&sAx[k][ty8];
            float4 x1 = *(const float4*)&sAx[k][ty8 + 4];
            float4 bl = *(const float4*)&sWl[k][tx4];
            float4 br = *(const float4*)&sWr[k][tx4];
            float a_[8] = {a0.x, a0.y, a0.z, a0.w, a1.x, a1.y, a1.z, a1.w};
            float x_[8] = {x0.x, x0.y, x0.z, x0.w, x1.x, x1.y, x1.z, x1.w};
            float l_[4] = {bl.x, bl.y, bl.z, bl.w};
            float r_[4] = {br.x, br.y, br.z, br.w};
            #pragma unroll
            for (int i = 0; i < 8; i++)
                #pragma unroll
                for (int j = 0; j < 4; j++)
                    acc[i][j] += a_[i] * l_[j] + x_[i] * r_[j];
        }
        __syncthreads();
    }

    #pragma unroll
    for (int i = 0; i < 8; i++) {
        int r = row0 + ty8 + i;
        if (r < N) {
            float4 o;
            o.x = acc[i][0] + bias[col0 + tx4 + 0];
            o.y = acc[i][1] + bias[col0 + tx4 + 1];
            o.z = acc[i][2] + bias[col0 + tx4 + 2];
            o.w = acc[i][3] + bias[col0 + tx4 + 3];
            if (relu) {
                o.x = fmaxf(o.x, 0.f); o.y = fmaxf(o.y, 0.f);
                o.z = fmaxf(o.z, 0.f); o.w = fmaxf(o.w, 0.f);
            }
            *(float4*)(Out + (size_t)r * M + col0 + tx4) = o;
        }
    }
}

// ---------------- single GEMM body: Out = A@W (+ optional bias) ----------------
__device__ __forceinline__ void gemm_single_body(
    const float* __restrict__ A, const float* __restrict__ W,
    const float* __restrict__ bias, float* __restrict__ Out,
    int N, int K, int M)
{
    __shared__ float sA[16][128];
    __shared__ float sW[16][64];

    const int tid = threadIdx.x;
    const int tx = tid & 15;
    const int ty = tid >> 4;
    const int tx4 = tx * 4, ty8 = ty * 8;
    const int row0 = blockIdx.y * 128;
    const int col0 = blockIdx.x * 64;

    const int ar = tid >> 1;
    const int ak = (tid & 1) * 8;
    const int wk = tid >> 4;
    const int wc = (tid & 15) * 4;

    const int arow = row0 + ar;
    const bool arow_ok = (arow < N);

    float acc[8][4];
    #pragma unroll
    for (int i = 0; i < 8; i++)
        #pragma unroll
        for (int j = 0; j < 4; j++) acc[i][j] = 0.f;

    for (int k0 = 0; k0 < K; k0 += 16) {
        float4 va0 = make_float4(0.f, 0.f, 0.f, 0.f), va1 = va0;
        if (arow_ok) {
            const float* ap = A + (size_t)arow * K + k0 + ak;
            va0 = *(const float4*)(ap);
            va1 = *(const float4*)(ap + 4);
        }
        sA[ak + 0][ar] = va0.x; sA[ak + 1][ar] = va0.y;
        sA[ak + 2][ar] = va0.z; sA[ak + 3][ar] = va0.w;
        sA[ak + 4][ar] = va1.x; sA[ak + 5][ar] = va1.y;
        sA[ak + 6][ar] = va1.z; sA[ak + 7][ar] = va1.w;

        *(float4*)&sW[wk][wc] = *(const float4*)(W + (size_t)(k0 + wk) * M + col0 + wc);

        __syncthreads();

        #pragma unroll
        for (int k = 0; k < 16; k++) {
            float4 a0 = *(const float4*)&sA[k][ty8];
            float4 a1 = *(const float4*)&sA[k][ty8 + 4];
            float4 wv = *(const float4*)&sW[k][tx4];
            float a_[8] = {a0.x, a0.y, a0.z, a0.w, a1.x, a1.y, a1.z, a1.w};
            float w_[4] = {wv.x, wv.y, wv.z, wv.w};
            #pragma unroll
            for (int i = 0; i < 8; i++)
                #pragma unroll
                for (int j = 0; j < 4; j++)
                    acc[i][j] += a_[i] * w_[j];
        }
        __syncthreads();
    }

    #pragma unroll
    for (int i = 0; i < 8; i++) {
        int r = row0 + ty8 + i;
        if (r < N) {
            float4 o;
            float bx = bias ? bias[col0 + tx4 + 0] : 0.f;
            float by = bias ? bias[col0 + tx4 + 1] : 0.f;
            float bz = bias ? bias[col0 + tx4 + 2] : 0.f;
            float bw = bias ? bias[col0 + tx4 + 3] : 0.f;
            o.x = acc[i][0] + bx; o.y = acc[i][1] + by;
            o.z = acc[i][2] + bz; o.w = acc[i][3] + bw;
            *(float4*)(Out + (size_t)r * M + col0 + tx4) = o;
        }
    }
}

// ---------------- GEMM wrappers binding scratch symbols (device side) ----------------
__global__ __launch_bounds__(256) void gemm_l1_k(
    const float* __restrict__ x, const float* __restrict__ W1l,
    const float* __restrict__ W1r, const float* __restrict__ b1)
{
    sage_gemm_body(g_z, x, W1l, W1r, b1, g_h, N_NODES, D_IN, D_HID, 1);
}

__global__ __launch_bounds__(256) void gemm_l2z_k(const float* __restrict__ W2l)
{
    gemm_single_body(g_h, W2l, nullptr, g_z, N_NODES, D_HID, D_OUT);
}

__global__ __launch_bounds__(256) void gemm_l2o_k(
    const float* __restrict__ W2r, const float* __restrict__ b2,
    float* __restrict__ out)
{
    gemm_single_body(g_h, W2r, b2, out, N_NODES, D_HID, D_OUT);
}

// ---------------- launch ----------------
extern "C" void kernel_launch(void* const* d_in, const int* in_sizes, int n_in,
                              void* d_out, int out_size) {
    const float* x   = (const float*)d_in[0];
    const void*  ei  = d_in[1];                 // int32 or int64; detected at runtime
    const float* W1l = (const float*)d_in[2];
    const float* b1  = (const float*)d_in[3];
    const float* W1r = (const float*)d_in[4];
    const float* W2l = (const float*)d_in[5];
    const float* b2  = (const float*)d_in[6];
    const float* W2r = (const float*)d_in[7];
    float*       out = (float*)d_out;

    // CSR build (per launch; deterministic)
    detect_k<<<1, 32>>>((const int*)ei);
    zero_cnt_k<<<(N_NODES + 255) / 256, 256>>>();
    count_k<<<(N_EDGES + 255) / 256, 256>>>(ei);
    scan_a_k<<<NBLK, 1024>>>();
    scan_b_k<<<1, 32>>>();
    scan_c_k<<<NBLK, 1024>>>();
    place_k<<<(N_EDGES + 255) / 256, 256>>>(ei);

    const int gather_blocks = (N_NODES * 32 + 255) / 256;
    const dim3 g1(D_HID / 64, (N_NODES + 127) / 128);
    const dim3 g2(D_OUT / 64, (N_NODES + 127) / 128);

    // Layer 1: g_z = mean_agg(x) ; g_h = relu(g_z@W1_l + x@W1_r + b1)
    gather_x_to_z_k<<<gather_blocks, 256>>>(x);
    gemm_l1_k<<<g1, 256>>>(x, W1l, W1r, b1);

    // Layer 2 (mean-linearity reorder):
    //   g_z = g_h@W2_l ; out = g_h@W2_r + b2 ; out += mean_agg(g_z)
    gemm_l2z_k<<<g2, 256>>>(W2l);
    gemm_l2o_k<<<g2, 256>>>(W2r, b2, out);
    gather_z_add_out_k<<<gather_blocks, 256>>>(out);
}

// round 13
// speedup vs baseline: 1.4730x; 1.3371x over previous
#include <cuda_runtime.h>
#include <cuda_bf16.h>
#include <mma.h>
#include <cstddef>

using namespace nvcuda;

#define N_NODES 50000
#define N_EDGES 800000
#define D_IN    128
#define D_HID   256
#define D_OUT   128
#define NBLK    49          // ceil(N_NODES / 1024)

// ---------------- device scratch (static, allocation-free) ----------------
__device__ int   g_is64;
__device__ int   g_cnt[N_NODES];
__device__ int   g_rowstart[N_NODES + 1];
__device__ int   g_work[N_NODES];
__device__ int   g_csr_src[N_EDGES];
__device__ int   g_blocksum[NBLK];
__device__ int   g_blockoff[NBLK + 1];
__device__ float g_z[(size_t)N_NODES * D_IN];  // layer1 agg; reused as z = h@W2_l
__device__ float g_h[(size_t)N_NODES * D_HID];

// ---------------- edge_index dtype detection ----------------
__global__ void detect_k(const int* __restrict__ ei32) {
    if (threadIdx.x == 0 && blockIdx.x == 0) {
        int is64 = 1;
        #pragma unroll
        for (int i = 1; i < 64; i += 2)
            if (ei32[i] != 0) is64 = 0;
        g_is64 = is64;
    }
}

__device__ __forceinline__ int load_edge(const void* ei, size_t idx, int is64) {
    if (is64) return (int)((const long long*)ei)[idx];
    return ((const int*)ei)[idx];
}

// ---------------- CSR build ----------------
__global__ void zero_cnt_k() {
    int i = blockIdx.x * blockDim.x + threadIdx.x;
    if (i < N_NODES) g_cnt[i] = 0;
}

__global__ void count_k(const void* __restrict__ ei) {
    int i = blockIdx.x * blockDim.x + threadIdx.x;
    if (i < N_EDGES) {
        int is64 = g_is64;
        int d = load_edge(ei, (size_t)N_EDGES + i, is64);
        if ((unsigned)d < (unsigned)N_NODES) atomicAdd(&g_cnt[d], 1);
    }
}

__global__ __launch_bounds__(1024) void scan_a_k() {
    __shared__ int wsum[32];
    int t = threadIdx.x, lane = t & 31, wid = t >> 5;
    int i = blockIdx.x * 1024 + t;
    int v = (i < N_NODES) ? g_cnt[i] : 0;
    #pragma unroll
    for (int off = 16; off > 0; off >>= 1)
        v += __shfl_down_sync(0xffffffffu, v, off);
    if (lane == 0) wsum[wid] = v;
    __syncthreads();
    if (wid == 0) {
        int w = wsum[lane];
        #pragma unroll
        for (int off = 16; off > 0; off >>= 1)
            w += __shfl_down_sync(0xffffffffu, w, off);
        if (lane == 0) g_blocksum[blockIdx.x] = w;
    }
}

__global__ void scan_b_k() {
    if (threadIdx.x == 0 && blockIdx.x == 0) {
        int run = 0;
        #pragma unroll
        for (int b = 0; b < NBLK; b++) {
            int s = g_blocksum[b];
            g_blockoff[b] = run;
            run += s;
        }
        g_blockoff[NBLK] = run;
        g_rowstart[N_NODES] = run;
    }
}

__global__ __launch_bounds__(1024) void scan_c_k() {
    __shared__ int wsum[32];
    int t = threadIdx.x, lane = t & 31, wid = t >> 5;
    int i = blockIdx.x * 1024 + t;
    int v = (i < N_NODES) ? g_cnt[i] : 0;

    int inc = v;
    #pragma unroll
    for (int off = 1; off < 32; off <<= 1) {
        int u = __shfl_up_sync(0xffffffffu, inc, off);
        if (lane >= off) inc += u;
    }
    if (lane == 31) wsum[wid] = inc;
    __syncthreads();
    if (wid == 0) {
        int w = wsum[lane];
        #pragma unroll
        for (int off = 1; off < 32; off <<= 1) {
            int u = __shfl_up_sync(0xffffffffu, w, off);
            if (lane >= off) w += u;
        }
        wsum[lane] = w;
    }
    __syncthreads();

    int excl = inc - v + (wid > 0 ? wsum[wid - 1] : 0) + g_blockoff[blockIdx.x];
    if (i < N_NODES) {
        g_rowstart[i] = excl;
        g_work[i]     = excl;
    }
}

__global__ void place_k(const void* __restrict__ ei) {
    int i = blockIdx.x * blockDim.x + threadIdx.x;
    if (i < N_EDGES) {
        int is64 = g_is64;
        int s = load_edge(ei, (size_t)i, is64);
        int d = load_edge(ei, (size_t)N_EDGES + i, is64);
        if ((unsigned)d < (unsigned)N_NODES && (unsigned)s < (unsigned)N_NODES) {
            int pos = atomicAdd(&g_work[d], 1);
            g_csr_src[pos] = s;
        }
    }
}

// ---------------- gather-mean: one warp per destination node (F=128) ----------------
template <int ADD>
__device__ __forceinline__ void gather128_body(const float* __restrict__ feat,
                                               float* __restrict__ agg) {
    int warp = (blockIdx.x * blockDim.x + threadIdx.x) >> 5;
    int lane = threadIdx.x & 31;
    if (warp >= N_NODES) return;
    int beg = g_rowstart[warp], end = g_rowstart[warp + 1];
    float4 acc = make_float4(0.f, 0.f, 0.f, 0.f);
    for (int e = beg; e < end; e++) {
        int s = g_csr_src[e];
        float4 v = ((const float4*)(feat + (size_t)s * 128))[lane];
        acc.x += v.x; acc.y += v.y; acc.z += v.z; acc.w += v.w;
    }
    int deg = end - beg;
    float scale = 1.0f / (float)(deg > 0 ? deg : 1);
    float4* o = (float4*)(agg + (size_t)warp * 128);
    float4 r;
    if (ADD) {
        float4 prev = o[lane];
        r.x = prev.x + acc.x * scale; r.y = prev.y + acc.y * scale;
        r.z = prev.z + acc.z * scale; r.w = prev.w + acc.w * scale;
    } else {
        r.x = acc.x * scale; r.y = acc.y * scale;
        r.z = acc.z * scale; r.w = acc.w * scale;
    }
    o[lane] = r;
}

__global__ void gather_x_to_z_k(const float* __restrict__ x) {
    gather128_body<0>(x, g_z);
}
__global__ void gather_z_add_out_k(float* __restrict__ out) {
    gather128_body<1>(g_z, out);
}

// ---------------- tf32 wmma GEMM (both layers) ----------------
// MODE 1 (layer 1): Out[N,256] = relu([A0 | A1] @ [W0 ; W1] + bias)
//   A0/A1: [N,128] (k-split at 128), W0/W1: [128,256], O0 = g_h.
// MODE 2 (layer 2): [O0 | O1] = A @ [W0 | W1] (col-split at 128)
//   A: [N,256] (A0=base, A1=base+128, stride 256), W0/W1: [256,128],
//   O0 = g_z (no bias), O1 = out (+bias).
// Tiles: BM=128, BN=64, BK=16; 8 warps (4x2), warp tile 32x32 (2x2 wmma 16x16x8).
#define KTOT 256
#define LDA  24
#define LDB  72
#define LDS_ 36

template <int MODE>
__device__ __forceinline__ void wmma_gemm_body(
    const float* __restrict__ A0, const float* __restrict__ A1,
    int sa0, int sa1,
    const float* __restrict__ W0, const float* __restrict__ W1,
    const float* __restrict__ bias,
    float* __restrict__ O0, float* __restrict__ O1)
{
    __shared__ float smem[9216];          // 36,864 B (union: loading / staging)
    float* sA = smem;                      // [128][LDA]
    float* sB = smem + 128 * LDA;          // [16][LDB]

    const int tid  = threadIdx.x;
    const int lane = tid & 31;
    const int wid  = tid >> 5;
    const int wm   = wid & 3;              // warp row 0..3
    const int wn   = wid >> 2;             // warp col 0..1
    const int row0 = blockIdx.y * 128;
    const int col0 = blockIdx.x * 64;

    // A loader mapping: 128 rows x 16 k; thread: r=tid>>1, kk=(tid&1)*8
    const int lr = tid >> 1;
    const int lk = (tid & 1) * 8;
    // B loader mapping: 16 k x 64 cols; thread: kk=tid>>4, c4=(tid&15)*4
    const int bk = tid >> 4;
    const int bc = (tid & 15) * 4;

    wmma::fragment<wmma::accumulator, 16, 16, 8, float> acc[2][2];
    #pragma unroll
    for (int i = 0; i < 2; i++)
        #pragma unroll
        for (int j = 0; j < 2; j++)
            wmma::fill_fragment(acc[i][j], 0.0f);

    for (int k0 = 0; k0 < KTOT; k0 += 16) {
        // ---- load A tile ----
        {
            int grow = row0 + lr;
            int gk = k0 + lk;
            float4 v0 = make_float4(0.f, 0.f, 0.f, 0.f), v1 = v0;
            if (grow < N_NODES) {
                const float* src = (gk < 128)
                    ? A0 + (size_t)grow * sa0 + gk
                    : A1 + (size_t)grow * sa1 + (gk - 128);
                v0 = *(const float4*)(src);
                v1 = *(const float4*)(src + 4);
            }
            float* d = &sA[lr * LDA + lk];
            d[0] = v0.x; d[1] = v0.y; d[2] = v0.z; d[3] = v0.w;
            d[4] = v1.x; d[5] = v1.y; d[6] = v1.z; d[7] = v1.w;
        }
        // ---- load B tile ----
        {
            int gk = k0 + bk;
            int gc = col0 + bc;
            const float* wsrc;
            if (MODE == 1) {
                wsrc = (gk < 128) ? W0 + (size_t)gk * 256 + gc
                                  : W1 + (size_t)(gk - 128) * 256 + gc;
            } else {
                wsrc = (gc < 128) ? W0 + (size_t)gk * 128 + gc
                                  : W1 + (size_t)gk * 128 + (gc - 128);
            }
            *(float4*)&sB[bk * LDB + bc] = *(const float4*)wsrc;
        }
        __syncthreads();

        #pragma unroll
        for (int kk8 = 0; kk8 < 16; kk8 += 8) {
            wmma::fragment<wmma::matrix_a, 16, 16, 8, wmma::precision::tf32, wmma::row_major> af[2];
            wmma::fragment<wmma::matrix_b, 16, 16, 8, wmma::precision::tf32, wmma::row_major> bf[2];
            #pragma unroll
            for (int i = 0; i < 2; i++) {
                wmma::load_matrix_sync(af[i], &sA[(wm * 32 + i * 16) * LDA + kk8], LDA);
                #pragma unroll
                for (int e = 0; e < af[i].num_elements; e++)
                    af[i].x[e] = wmma::__float_to_tf32(af[i].x[e]);
            }
            #pragma unroll
            for (int j = 0; j < 2; j++) {
                wmma::load_matrix_sync(bf[j], &sB[kk8 * LDB + wn * 32 + j * 16], LDB);
                #pragma unroll
                for (int e = 0; e < bf[j].num_elements; e++)
                    bf[j].x[e] = wmma::__float_to_tf32(bf[j].x[e]);
            }
            #pragma unroll
            for (int i = 0; i < 2; i++)
                #pragma unroll
                for (int j = 0; j < 2; j++)
                    wmma::mma_sync(acc[i][j], af[i], bf[j], acc[i][j]);
        }
        __syncthreads();
    }

    // ---- epilogue: stage warp tile 32x32 in smem, then coalesced global write ----
    float* stg = smem + wid * 32 * LDS_;
    #pragma unroll
    for (int i = 0; i < 2; i++)
        #pragma unroll
        for (int j = 0; j < 2; j++)
            wmma::store_matrix_sync(&stg[(i * 16) * LDS_ + j * 16], acc[i][j],
                                    LDS_, wmma::mem_row_major);
    __syncwarp();

    int grow = row0 + wm * 32 + lane;
    if (grow < N_NODES) {
        int gcol0 = col0 + wn * 32;
        #pragma unroll
        for (int c4 = 0; c4 < 8; c4++) {
            float4 v = *(float4*)&stg[lane * LDS_ + c4 * 4];
            int gc = gcol0 + c4 * 4;
            if (MODE == 1) {
                v.x += bias[gc + 0]; v.y += bias[gc + 1];
                v.z += bias[gc + 2]; v.w += bias[gc + 3];
                v.x = fmaxf(v.x, 0.f); v.y = fmaxf(v.y, 0.f);
                v.z = fmaxf(v.z, 0.f); v.w = fmaxf(v.w, 0.f);
                *(float4*)(O0 + (size_t)grow * 256 + gc) = v;
            } else {
                if (gc < 128) {
                    *(float4*)(O0 + (size_t)grow * 128 + gc) = v;
                } else {
                    int c = gc - 128;
                    v.x += bias[c + 0]; v.y += bias[c + 1];
                    v.z += bias[c + 2]; v.w += bias[c + 3];
                    *(float4*)(O1 + (size_t)grow * 128 + c) = v;
                }
            }
        }
    }
}

// wrappers binding scratch symbols on the device side
__global__ __launch_bounds__(256) void gemm1_k(
    const float* __restrict__ x, const float* __restrict__ W1l,
    const float* __restrict__ W1r, const float* __restrict__ b1)
{
    wmma_gemm_body<1>(g_z, x, D_IN, D_IN, W1l, W1r, b1, g_h, nullptr);
}

__global__ __launch_bounds__(256) void gemm2_k(
    const float* __restrict__ W2l, const float* __restrict__ W2r,
    const float* __restrict__ b2, float* __restrict__ out)
{
    wmma_gemm_body<2>(g_h, g_h + 128, D_HID, D_HID, W2l, W2r, b2, g_z, out);
}

// ---------------- launch ----------------
extern "C" void kernel_launch(void* const* d_in, const int* in_sizes, int n_in,
                              void* d_out, int out_size) {
    const float* x   = (const float*)d_in[0];
    const void*  ei  = d_in[1];                 // int32 or int64; detected at runtime
    const float* W1l = (const float*)d_in[2];
    const float* b1  = (const float*)d_in[3];
    const float* W1r = (const float*)d_in[4];
    const float* W2l = (const float*)d_in[5];
    const float* b2  = (const float*)d_in[6];
    const float* W2r = (const float*)d_in[7];
    float*       out = (float*)d_out;

    // CSR build (per launch; deterministic)
    detect_k<<<1, 32>>>((const int*)ei);
    zero_cnt_k<<<(N_NODES + 255) / 256, 256>>>();
    count_k<<<(N_EDGES + 255) / 256, 256>>>(ei);
    scan_a_k<<<NBLK, 1024>>>();
    scan_b_k<<<1, 32>>>();
    scan_c_k<<<NBLK, 1024>>>();
    place_k<<<(N_EDGES + 255) / 256, 256>>>(ei);

    const int gather_blocks = (N_NODES * 32 + 255) / 256;
    const dim3 gg(256 / 64, (N_NODES + 127) / 128);   // 4 x 391

    // Layer 1: g_z = mean_agg(x) ; g_h = relu([g_z|x]@[W1l;W1r] + b1)
    gather_x_to_z_k<<<gather_blocks, 256>>>(x);
    gemm1_k<<<gg, 256>>>(x, W1l, W1r, b1);

    // Layer 2: [g_z | out] = g_h@[W2l | W2r] (+b2 on out) ; out += mean_agg(g_z)
    gemm2_k<<<gg, 256>>>(W2l, W2r, b2, out);
    gather_z_add_out_k<<<gather_blocks, 256>>>(out);
}

// round 14
// speedup vs baseline: 1.4977x; 1.0168x over previous
#include <cuda_runtime.h>
#include <cuda_bf16.h>
#include <mma.h>
#include <cstddef>

using namespace nvcuda;

#define N_NODES 50000
#define N_EDGES 800000
#define D_IN    128
#define D_HID   256
#define D_OUT   128
#define NBLK    49          // ceil(N_NODES / 1024)

// ---------------- device scratch (static, allocation-free) ----------------
__device__ int   g_is64;
__device__ int   g_cnt[N_NODES];
__device__ int   g_rowstart[N_NODES + 1];
__device__ int   g_work[N_NODES];
__device__ int   g_csr_src[N_EDGES];
__device__ int   g_blocksum[NBLK];
__device__ float g_z[(size_t)N_NODES * D_IN];  // layer1 agg; reused as z = h@W2_l
__device__ float g_h[(size_t)N_NODES * D_HID];

// ---------------- edge_index dtype detection ----------------
__global__ void detect_k(const int* __restrict__ ei32) {
    if (threadIdx.x == 0 && blockIdx.x == 0) {
        int is64 = 1;
        #pragma unroll
        for (int i = 1; i < 64; i += 2)
            if (ei32[i] != 0) is64 = 0;
        g_is64 = is64;
    }
}

__device__ __forceinline__ int load_edge(const void* ei, size_t idx, int is64) {
    if (is64) return (int)((const long long*)ei)[idx];
    return ((const int*)ei)[idx];
}

// ---------------- CSR build ----------------
__global__ void zero_cnt_k() {
    int i = blockIdx.x * blockDim.x + threadIdx.x;
    if (i < N_NODES) g_cnt[i] = 0;
}

__global__ void count_k(const void* __restrict__ ei) {
    int i = blockIdx.x * blockDim.x + threadIdx.x;
    if (i < N_EDGES) {
        int is64 = g_is64;
        int d = load_edge(ei, (size_t)N_EDGES + i, is64);
        if ((unsigned)d < (unsigned)N_NODES) atomicAdd(&g_cnt[d], 1);
    }
}

// pass A: per-block tile reduction (coalesced)
__global__ __launch_bounds__(1024) void scan_a_k() {
    __shared__ int wsum[32];
    int t = threadIdx.x, lane = t & 31, wid = t >> 5;
    int i = blockIdx.x * 1024 + t;
    int v = (i < N_NODES) ? g_cnt[i] : 0;
    #pragma unroll
    for (int off = 16; off > 0; off >>= 1)
        v += __shfl_down_sync(0xffffffffu, v, off);
    if (lane == 0) wsum[wid] = v;
    __syncthreads();
    if (wid == 0) {
        int w = wsum[lane];
        #pragma unroll
        for (int off = 16; off > 0; off >>= 1)
            w += __shfl_down_sync(0xffffffffu, w, off);
        if (lane == 0) g_blocksum[blockIdx.x] = w;
    }
}

// pass C (scan_b fused): per-block exclusive scan + locally-computed block offset
__global__ __launch_bounds__(1024) void scan_c_k() {
    __shared__ int wsum[32];
    __shared__ int blk_off, total_sh;
    int t = threadIdx.x, lane = t & 31, wid = t >> 5;
    int bid = blockIdx.x;

    // warp 0 computes this block's offset (sum of blocksum[0..bid-1]) and total
    if (wid == 0) {
        int s0 = (lane < NBLK) ? g_blocksum[lane] : 0;
        int s1 = (lane + 32 < NBLK) ? g_blocksum[lane + 32] : 0;
        int pre = ((lane < bid) ? s0 : 0) + ((lane + 32 < bid) ? s1 : 0);
        int tot = s0 + s1;
        #pragma unroll
        for (int off = 16; off > 0; off >>= 1) {
            pre += __shfl_down_sync(0xffffffffu, pre, off);
            tot += __shfl_down_sync(0xffffffffu, tot, off);
        }
        if (lane == 0) { blk_off = pre; total_sh = tot; }
    }

    int i = bid * 1024 + t;
    int v = (i < N_NODES) ? g_cnt[i] : 0;

    int inc = v;
    #pragma unroll
    for (int off = 1; off < 32; off <<= 1) {
        int u = __shfl_up_sync(0xffffffffu, inc, off);
        if (lane >= off) inc += u;
    }
    if (lane == 31) wsum[wid] = inc;
    __syncthreads();
    if (wid == 0) {
        int w = wsum[lane];
        #pragma unroll
        for (int off = 1; off < 32; off <<= 1) {
            int u = __shfl_up_sync(0xffffffffu, w, off);
            if (lane >= off) w += u;
        }
        wsum[lane] = w;
    }
    __syncthreads();

    int excl = inc - v + (wid > 0 ? wsum[wid - 1] : 0) + blk_off;
    if (i < N_NODES) {
        g_rowstart[i] = excl;
        g_work[i]     = excl;
    }
    if (bid == 0 && t == 0) g_rowstart[N_NODES] = total_sh;
}

__global__ void place_k(const void* __restrict__ ei) {
    int i = blockIdx.x * blockDim.x + threadIdx.x;
    if (i < N_EDGES) {
        int is64 = g_is64;
        int s = load_edge(ei, (size_t)i, is64);
        int d = load_edge(ei, (size_t)N_EDGES + i, is64);
        if ((unsigned)d < (unsigned)N_NODES && (unsigned)s < (unsigned)N_NODES) {
            int pos = atomicAdd(&g_work[d], 1);
            g_csr_src[pos] = s;
        }
    }
}

// ---------------- gather-mean: one warp per destination node (F=128) ----------------
// edge loop unrolled x4 for memory-level parallelism
template <int ADD>
__device__ __forceinline__ void gather128_body(const float* __restrict__ feat,
                                               float* __restrict__ agg) {
    int warp = (blockIdx.x * blockDim.x + threadIdx.x) >> 5;
    int lane = threadIdx.x & 31;
    if (warp >= N_NODES) return;
    int beg = g_rowstart[warp], end = g_rowstart[warp + 1];
    float4 acc = make_float4(0.f, 0.f, 0.f, 0.f);

    int e = beg;
    for (; e + 4 <= end; e += 4) {
        int s0 = g_csr_src[e + 0];
        int s1 = g_csr_src[e + 1];
        int s2 = g_csr_src[e + 2];
        int s3 = g_csr_src[e + 3];
        float4 v0 = ((const float4*)(feat + (size_t)s0 * 128))[lane];
        float4 v1 = ((const float4*)(feat + (size_t)s1 * 128))[lane];
        float4 v2 = ((const float4*)(feat + (size_t)s2 * 128))[lane];
        float4 v3 = ((const float4*)(feat + (size_t)s3 * 128))[lane];
        acc.x += v0.x + v1.x + v2.x + v3.x;
        acc.y += v0.y + v1.y + v2.y + v3.y;
        acc.z += v0.z + v1.z + v2.z + v3.z;
        acc.w += v0.w + v1.w + v2.w + v3.w;
    }
    for (; e < end; e++) {
        int s = g_csr_src[e];
        float4 v = ((const float4*)(feat + (size_t)s * 128))[lane];
        acc.x += v.x; acc.y += v.y; acc.z += v.z; acc.w += v.w;
    }

    int deg = end - beg;
    float scale = 1.0f / (float)(deg > 0 ? deg : 1);
    float4* o = (float4*)(agg + (size_t)warp * 128);
    float4 r;
    if (ADD) {
        float4 prev = o[lane];
        r.x = prev.x + acc.x * scale; r.y = prev.y + acc.y * scale;
        r.z = prev.z + acc.z * scale; r.w = prev.w + acc.w * scale;
    } else {
        r.x = acc.x * scale; r.y = acc.y * scale;
        r.z = acc.z * scale; r.w = acc.w * scale;
    }
    o[lane] = r;
}

__global__ void gather_x_to_z_k(const float* __restrict__ x) {
    gather128_body<0>(x, g_z);
}
__global__ void gather_z_add_out_k(float* __restrict__ out) {
    gather128_body<1>(g_z, out);
}

// ---------------- tf32 wmma GEMM (both layers), software-pipelined ----------------
// MODE 1 (layer 1): Out[N,256] = relu([A0 | A1] @ [W0 ; W1] + bias); O0 = g_h
// MODE 2 (layer 2): [O0 | O1] = A @ [W0 | W1]; O0 = g_z, O1 = out (+bias)
// Tiles: BM=128, BN=64, BK=16; 8 warps (4x2), warp tile 32x32 (2x2 wmma 16x16x8).
#define KTOT 256
#define LDA  24
#define LDB  72
#define LDS_ 36

template <int MODE>
__device__ __forceinline__ void wmma_gemm_body(
    const float* __restrict__ A0, const float* __restrict__ A1,
    int sa0, int sa1,
    const float* __restrict__ W0, const float* __restrict__ W1,
    const float* __restrict__ bias,
    float* __restrict__ O0, float* __restrict__ O1)
{
    __shared__ float smem[9216];          // 36,864 B (union: loading / staging)
    float* sA = smem;                      // [128][LDA]
    float* sB = smem + 128 * LDA;          // [16][LDB]

    const int tid  = threadIdx.x;
    const int lane = tid & 31;
    const int wid  = tid >> 5;
    const int wm   = wid & 3;
    const int wn   = wid >> 2;
    const int row0 = blockIdx.y * 128;
    const int col0 = blockIdx.x * 64;

    const int lr = tid >> 1;
    const int lk = (tid & 1) * 8;
    const int bk = tid >> 4;
    const int bc = (tid & 15) * 4;

    const int grow_a = row0 + lr;
    const bool arow_ok = (grow_a < N_NODES);

    wmma::fragment<wmma::accumulator, 16, 16, 8, float> acc[2][2];
    #pragma unroll
    for (int i = 0; i < 2; i++)
        #pragma unroll
        for (int j = 0; j < 2; j++)
            wmma::fill_fragment(acc[i][j], 0.0f);

    // tile-fetch into registers
    float4 ra0, ra1, rb;
    auto fetch = [&](int k0) {
        ra0 = make_float4(0.f, 0.f, 0.f, 0.f); ra1 = ra0;
        int gk = k0 + lk;
        if (arow_ok) {
            const float* src = (gk < 128)
                ? A0 + (size_t)grow_a * sa0 + gk
                : A1 + (size_t)grow_a * sa1 + (gk - 128);
            ra0 = *(const float4*)(src);
            ra1 = *(const float4*)(src + 4);
        }
        int gkb = k0 + bk;
        int gc = col0 + bc;
        const float* wsrc;
        if (MODE == 1) {
            wsrc = (gkb < 128) ? W0 + (size_t)gkb * 256 + gc
                               : W1 + (size_t)(gkb - 128) * 256 + gc;
        } else {
            wsrc = (gc < 128) ? W0 + (size_t)gkb * 128 + gc
                              : W1 + (size_t)gkb * 128 + (gc - 128);
        }
        rb = *(const float4*)wsrc;
    };
    auto commit = [&]() {
        float* d = &sA[lr * LDA + lk];
        d[0] = ra0.x; d[1] = ra0.y; d[2] = ra0.z; d[3] = ra0.w;
        d[4] = ra1.x; d[5] = ra1.y; d[6] = ra1.z; d[7] = ra1.w;
        *(float4*)&sB[bk * LDB + bc] = rb;
    };

    fetch(0);
    for (int k0 = 0; k0 < KTOT; k0 += 16) {
        commit();
        __syncthreads();
        if (k0 + 16 < KTOT) fetch(k0 + 16);   // prefetch next tile during MMAs

        #pragma unroll
        for (int kk8 = 0; kk8 < 16; kk8 += 8) {
            wmma::fragment<wmma::matrix_a, 16, 16, 8, wmma::precision::tf32, wmma::row_major> af[2];
            wmma::fragment<wmma::matrix_b, 16, 16, 8, wmma::precision::tf32, wmma::row_major> bf[2];
            #pragma unroll
            for (int i = 0; i < 2; i++) {
                wmma::load_matrix_sync(af[i], &sA[(wm * 32 + i * 16) * LDA + kk8], LDA);
                #pragma unroll
                for (int e = 0; e < af[i].num_elements; e++)
                    af[i].x[e] = wmma::__float_to_tf32(af[i].x[e]);
            }
            #pragma unroll
            for (int j = 0; j < 2; j++) {
                wmma::load_matrix_sync(bf[j], &sB[kk8 * LDB + wn * 32 + j * 16], LDB);
                #pragma unroll
                for (int e = 0; e < bf[j].num_elements; e++)
                    bf[j].x[e] = wmma::__float_to_tf32(bf[j].x[e]);
            }
            #pragma unroll
            for (int i = 0; i < 2; i++)
                #pragma unroll
                for (int j = 0; j < 2; j++)
                    wmma::mma_sync(acc[i][j], af[i], bf[j], acc[i][j]);
        }
        __syncthreads();
    }

    // ---- epilogue: stage warp tile 32x32 in smem, then coalesced global write ----
    float* stg = smem + wid * 32 * LDS_;
    #pragma unroll
    for (int i = 0; i < 2; i++)
        #pragma unroll
        for (int j = 0; j < 2; j++)
            wmma::store_matrix_sync(&stg[(i * 16) * LDS_ + j * 16], acc[i][j],
                                    LDS_, wmma::mem_row_major);
    __syncwarp();

    int grow = row0 + wm * 32 + lane;
    if (grow < N_NODES) {
        int gcol0 = col0 + wn * 32;
        #pragma unroll
        for (int c4 = 0; c4 < 8; c4++) {
            float4 v = *(float4*)&stg[lane * LDS_ + c4 * 4];
            int gc = gcol0 + c4 * 4;
            if (MODE == 1) {
                v.x += bias[gc + 0]; v.y += bias[gc + 1];
                v.z += bias[gc + 2]; v.w += bias[gc + 3];
                v.x = fmaxf(v.x, 0.f); v.y = fmaxf(v.y, 0.f);
                v.z = fmaxf(v.z, 0.f); v.w = fmaxf(v.w, 0.f);
                *(float4*)(O0 + (size_t)grow * 256 + gc) = v;
            } else {
                if (gc < 128) {
                    *(float4*)(O0 + (size_t)grow * 128 + gc) = v;
                } else {
                    int c = gc - 128;
                    v.x += bias[c + 0]; v.y += bias[c + 1];
                    v.z += bias[c + 2]; v.w += bias[c + 3];
                    *(float4*)(O1 + (size_t)grow * 128 + c) = v;
                }
            }
        }
    }
}

// wrappers binding scratch symbols on the device side
__global__ __launch_bounds__(256) void gemm1_k(
    const float* __restrict__ x, const float* __restrict__ W1l,
    const float* __restrict__ W1r, const float* __restrict__ b1)
{
    wmma_gemm_body<1>(g_z, x, D_IN, D_IN, W1l, W1r, b1, g_h, nullptr);
}

__global__ __launch_bounds__(256) void gemm2_k(
    const float* __restrict__ W2l, const float* __restrict__ W2r,
    const float* __restrict__ b2, float* __restrict__ out)
{
    wmma_gemm_body<2>(g_h, g_h + 128, D_HID, D_HID, W2l, W2r, b2, g_z, out);
}

// ---------------- launch ----------------
extern "C" void kernel_launch(void* const* d_in, const int* in_sizes, int n_in,
                              void* d_out, int out_size) {
    const float* x   = (const float*)d_in[0];
    const void*  ei  = d_in[1];                 // int32 or int64; detected at runtime
    const float* W1l = (const float*)d_in[2];
    const float* b1  = (const float*)d_in[3];
    const float* W1r = (const float*)d_in[4];
    const float* W2l = (const float*)d_in[5];
    const float* b2  = (const float*)d_in[6];
    const float* W2r = (const float*)d_in[7];
    float*       out = (float*)d_out;

    // CSR build (per launch; deterministic)
    detect_k<<<1, 32>>>((const int*)ei);
    zero_cnt_k<<<(N_NODES + 255) / 256, 256>>>();
    count_k<<<(N_EDGES + 255) / 256, 256>>>(ei);
    scan_a_k<<<NBLK, 1024>>>();
    scan_c_k<<<NBLK, 1024>>>();
    place_k<<<(N_EDGES + 255) / 256, 256>>>(ei);

    const int gather_blocks = (N_NODES * 32 + 255) / 256;
    const dim3 gg(256 / 64, (N_NODES + 127) / 128);   // 4 x 391

    // Layer 1: g_z = mean_agg(x) ; g_h = relu([g_z|x]@[W1l;W1r] + b1)
    gather_x_to_z_k<<<gather_blocks, 256>>>(x);
    gemm1_k<<<gg, 256>>>(x, W1l, W1r, b1);

    // Layer 2: [g_z | out] = g_h@[W2l | W2r] (+b2 on out) ; out += mean_agg(g_z)
    gemm2_k<<<gg, 256>>>(W2l, W2r, b2, out);
    gather_z_add_out_k<<<gather_blocks, 256>>>(out);
}

// round 16
// speedup vs baseline: 1.5080x; 1.0069x over previous
#include <cuda_runtime.h>
#include <cuda_bf16.h>
#include <mma.h>
#include <cstddef>

using namespace nvcuda;

#define N_NODES 50000
#define N_EDGES 800000
#define D_IN    128
#define D_HID   256
#define D_OUT   128
#define NBLK    49          // ceil(N_NODES / 1024)

// ---------------- device scratch (static, allocation-free) ----------------
__device__ int   g_is64;
__device__ int   g_cnt[N_NODES];
__device__ int   g_rowstart[N_NODES + 1];
__device__ int   g_work[N_NODES];
__device__ int   g_csr_src[N_EDGES];
__device__ int   g_blocksum[NBLK];
__device__ float g_z[(size_t)N_NODES * D_IN];  // layer1 agg; reused as z = h@W2_l
__device__ float g_h[(size_t)N_NODES * D_HID];

// ---------------- CSR build ----------------
// zero counters; block 0/thread 0 also detects edge_index dtype
// (int64 little-endian < 2^31 => every odd 32-bit word is 0)
__global__ void zero_cnt_k(const int* __restrict__ ei32) {
    int i = blockIdx.x * blockDim.x + threadIdx.x;
    if (i < N_NODES) g_cnt[i] = 0;
    if (i == 0) {
        int is64 = 1;
        #pragma unroll
        for (int j = 1; j < 64; j += 2)
            if (ei32[j] != 0) is64 = 0;
        g_is64 = is64;
    }
}

__device__ __forceinline__ int load_edge(const void* ei, size_t idx, int is64) {
    if (is64) return (int)((const long long*)ei)[idx];
    return ((const int*)ei)[idx];
}

__global__ void count_k(const void* __restrict__ ei) {
    int i = blockIdx.x * blockDim.x + threadIdx.x;
    if (i < N_EDGES) {
        int is64 = g_is64;
        int d = load_edge(ei, (size_t)N_EDGES + i, is64);
        if ((unsigned)d < (unsigned)N_NODES) atomicAdd(&g_cnt[d], 1);
    }
}

// pass A: per-block tile reduction (coalesced)
__global__ __launch_bounds__(1024) void scan_a_k() {
    __shared__ int wsum[32];
    int t = threadIdx.x, lane = t & 31, wid = t >> 5;
    int i = blockIdx.x * 1024 + t;
    int v = (i < N_NODES) ? g_cnt[i] : 0;
    #pragma unroll
    for (int off = 16; off > 0; off >>= 1)
        v += __shfl_down_sync(0xffffffffu, v, off);
    if (lane == 0) wsum[wid] = v;
    __syncthreads();
    if (wid == 0) {
        int w = wsum[lane];
        #pragma unroll
        for (int off = 16; off > 0; off >>= 1)
            w += __shfl_down_sync(0xffffffffu, w, off);
        if (lane == 0) g_blocksum[blockIdx.x] = w;
    }
}

// pass C: per-block exclusive scan + locally-computed block offset
__global__ __launch_bounds__(1024) void scan_c_k() {
    __shared__ int wsum[32];
    __shared__ int blk_off, total_sh;
    int t = threadIdx.x, lane = t & 31, wid = t >> 5;
    int bid = blockIdx.x;

    if (wid == 0) {
        int s0 = (lane < NBLK) ? g_blocksum[lane] : 0;
        int s1 = (lane + 32 < NBLK) ? g_blocksum[lane + 32] : 0;
        int pre = ((lane < bid) ? s0 : 0) + ((lane + 32 < bid) ? s1 : 0);
        int tot = s0 + s1;
        #pragma unroll
        for (int off = 16; off > 0; off >>= 1) {
            pre += __shfl_down_sync(0xffffffffu, pre, off);
            tot += __shfl_down_sync(0xffffffffu, tot, off);
        }
        if (lane == 0) { blk_off = pre; total_sh = tot; }
    }

    int i = bid * 1024 + t;
    int v = (i < N_NODES) ? g_cnt[i] : 0;

    int inc = v;
    #pragma unroll
    for (int off = 1; off < 32; off <<= 1) {
        int u = __shfl_up_sync(0xffffffffu, inc, off);
        if (lane >= off) inc += u;
    }
    if (lane == 31) wsum[wid] = inc;
    __syncthreads();
    if (wid == 0) {
        int w = wsum[lane];
        #pragma unroll
        for (int off = 1; off < 32; off <<= 1) {
            int u = __shfl_up_sync(0xffffffffu, w, off);
            if (lane >= off) w += u;
        }
        wsum[lane] = w;
    }
    __syncthreads();

    int excl = inc - v + (wid > 0 ? wsum[wid - 1] : 0) + blk_off;
    if (i < N_NODES) {
        g_rowstart[i] = excl;
        g_work[i]     = excl;
    }
    if (bid == 0 && t == 0) g_rowstart[N_NODES] = total_sh;
}

__global__ void place_k(const void* __restrict__ ei) {
    int i = blockIdx.x * blockDim.x + threadIdx.x;
    if (i < N_EDGES) {
        int is64 = g_is64;
        int s = load_edge(ei, (size_t)i, is64);
        int d = load_edge(ei, (size_t)N_EDGES + i, is64);
        if ((unsigned)d < (unsigned)N_NODES && (unsigned)s < (unsigned)N_NODES) {
            int pos = atomicAdd(&g_work[d], 1);
            g_csr_src[pos] = s;
        }
    }
}

// ---------------- gather-mean: one warp per destination node (F=128) ----------------
template <int ADD>
__device__ __forceinline__ void gather128_body(const float* __restrict__ feat,
                                               float* __restrict__ agg) {
    int warp = (blockIdx.x * blockDim.x + threadIdx.x) >> 5;
    int lane = threadIdx.x & 31;
    if (warp >= N_NODES) return;
    int beg = g_rowstart[warp], end = g_rowstart[warp + 1];
    float4 acc = make_float4(0.f, 0.f, 0.f, 0.f);

    int e = beg;
    for (; e + 4 <= end; e += 4) {
        int s0 = g_csr_src[e + 0];
        int s1 = g_csr_src[e + 1];
        int s2 = g_csr_src[e + 2];
        int s3 = g_csr_src[e + 3];
        float4 v0 = ((const float4*)(feat + (size_t)s0 * 128))[lane];
        float4 v1 = ((const float4*)(feat + (size_t)s1 * 128))[lane];
        float4 v2 = ((const float4*)(feat + (size_t)s2 * 128))[lane];
        float4 v3 = ((const float4*)(feat + (size_t)s3 * 128))[lane];
        acc.x += v0.x + v1.x + v2.x + v3.x;
        acc.y += v0.y + v1.y + v2.y + v3.y;
        acc.z += v0.z + v1.z + v2.z + v3.z;
        acc.w += v0.w + v1.w + v2.w + v3.w;
    }
    for (; e < end; e++) {
        int s = g_csr_src[e];
        float4 v = ((const float4*)(feat + (size_t)s * 128))[lane];
        acc.x += v.x; acc.y += v.y; acc.z += v.z; acc.w += v.w;
    }

    int deg = end - beg;
    float scale = 1.0f / (float)(deg > 0 ? deg : 1);
    float4* o = (float4*)(agg + (size_t)warp * 128);
    float4 r;
    if (ADD) {
        float4 prev = o[lane];
        r.x = prev.x + acc.x * scale; r.y = prev.y + acc.y * scale;
        r.z = prev.z + acc.z * scale; r.w = prev.w + acc.w * scale;
    } else {
        r.x = acc.x * scale; r.y = acc.y * scale;
        r.z = acc.z * scale; r.w = acc.w * scale;
    }
    o[lane] = r;
}

__global__ void gather_x_to_z_k(const float* __restrict__ x) {
    gather128_body<0>(x, g_z);
}
__global__ void gather_z_add_out_k(float* __restrict__ out) {
    gather128_body<1>(g_z, out);
}

// ---------------- tf32 wmma GEMM (both layers), software-pipelined ----------------
// MODE 1 (layer 1): Out[N,256] = relu([A0 | A1] @ [W0 ; W1] + bias); O0 = g_h
// MODE 2 (layer 2): [O0 | O1] = A @ [W0 | W1]; O0 = g_z, O1 = out (+bias)
// Tiles: BM=128, BN=64, BK=16; 8 warps (4x2), warp tile 32x32 (2x2 wmma 16x16x8).
// Pad strides to kill bank conflicts: LDA=36 (4r mod 32, period 8 -> 2-way over
// 16-row A frags), LDB=68 (period 8 -> conflict-free over 8-row B frags).
#define KTOT 256
#define LDA  36
#define LDB  68
#define LDS_ 36

template <int MODE>
__device__ __forceinline__ void wmma_gemm_body(
    const float* __restrict__ A0, const float* __restrict__ A1,
    int sa0, int sa1,
    const float* __restrict__ W0, const float* __restrict__ W1,
    const float* __restrict__ bias,
    float* __restrict__ O0, float* __restrict__ O1)
{
    __shared__ float smem[9216];          // 36,864 B (union: loading / staging)
    float* sA = smem;                      // [128][LDA] = 4608 floats
    float* sB = smem + 128 * LDA;          // [16][LDB] = 1088 floats (total 5696 < 9216)

    const int tid  = threadIdx.x;
    const int lane = tid & 31;
    const int wid  = tid >> 5;
    const int wm   = wid & 3;
    const int wn   = wid >> 2;
    const int row0 = blockIdx.y * 128;
    const int col0 = blockIdx.x * 64;

    const int lr = tid >> 1;
    const int lk = (tid & 1) * 8;
    const int bk = tid >> 4;
    const int bc = (tid & 15) * 4;

    const int grow_a = row0 + lr;
    const bool arow_ok = (grow_a < N_NODES);

    wmma::fragment<wmma::accumulator, 16, 16, 8, float> acc[2][2];
    #pragma unroll
    for (int i = 0; i < 2; i++)
        #pragma unroll
        for (int j = 0; j < 2; j++)
            wmma::fill_fragment(acc[i][j], 0.0f);

    float4 ra0, ra1, rb;
    auto fetch = [&](int k0) {
        ra0 = make_float4(0.f, 0.f, 0.f, 0.f); ra1 = ra0;
        int gk = k0 + lk;
        if (arow_ok) {
            const float* src = (gk < 128)
                ? A0 + (size_t)grow_a * sa0 + gk
                : A1 + (size_t)grow_a * sa1 + (gk - 128);
            ra0 = *(const float4*)(src);
            ra1 = *(const float4*)(src + 4);
        }
        int gkb = k0 + bk;
        int gc = col0 + bc;
        const float* wsrc;
        if (MODE == 1) {
            wsrc = (gkb < 128) ? W0 + (size_t)gkb * 256 + gc
                               : W1 + (size_t)(gkb - 128) * 256 + gc;
        } else {
            wsrc = (gc < 128) ? W0 + (size_t)gkb * 128 + gc
                              : W1 + (size_t)gkb * 128 + (gc - 128);
        }
        rb = *(const float4*)wsrc;
    };
    auto commit = [&]() {
        float* d = &sA[lr * LDA + lk];
        d[0] = ra0.x; d[1] = ra0.y; d[2] = ra0.z; d[3] = ra0.w;
        d[4] = ra1.x; d[5] = ra1.y; d[6] = ra1.z; d[7] = ra1.w;
        *(float4*)&sB[bk * LDB + bc] = rb;
    };

    fetch(0);
    for (int k0 = 0; k0 < KTOT; k0 += 16) {
        commit();
        __syncthreads();
        if (k0 + 16 < KTOT) fetch(k0 + 16);

        #pragma unroll
        for (int kk8 = 0; kk8 < 16; kk8 += 8) {
            wmma::fragment<wmma::matrix_a, 16, 16, 8, wmma::precision::tf32, wmma::row_major> af[2];
            wmma::fragment<wmma::matrix_b, 16, 16, 8, wmma::precision::tf32, wmma::row_major> bf[2];
            #pragma unroll
            for (int i = 0; i < 2; i++) {
                wmma::load_matrix_sync(af[i], &sA[(wm * 32 + i * 16) * LDA + kk8], LDA);
                #pragma unroll
                for (int e = 0; e < af[i].num_elements; e++)
                    af[i].x[e] = wmma::__float_to_tf32(af[i].x[e]);
            }
            #pragma unroll
            for (int j = 0; j < 2; j++) {
                wmma::load_matrix_sync(bf[j], &sB[kk8 * LDB + wn * 32 + j * 16], LDB);
                #pragma unroll
                for (int e = 0; e < bf[j].num_elements; e++)
                    bf[j].x[e] = wmma::__float_to_tf32(bf[j].x[e]);
            }
            #pragma unroll
            for (int i = 0; i < 2; i++)
                #pragma unroll
                for (int j = 0; j < 2; j++)
                    wmma::mma_sync(acc[i][j], af[i], bf[j], acc[i][j]);
        }
        __syncthreads();
    }

    // ---- epilogue: stage warp tile 32x32 in smem, then coalesced global write ----
    float* stg = smem + wid * 32 * LDS_;
    #pragma unroll
    for (int i = 0; i < 2; i++)
        #pragma unroll
        for (int j = 0; j < 2; j++)
            wmma::store_matrix_sync(&stg[(i * 16) * LDS_ + j * 16], acc[i][j],
                                    LDS_, wmma::mem_row_major);
    __syncwarp();

    int grow = row0 + wm * 32 + lane;
    if (grow < N_NODES) {
        int gcol0 = col0 + wn * 32;
        #pragma unroll
        for (int c4 = 0; c4 < 8; c4++) {
            float4 v = *(float4*)&stg[lane * LDS_ + c4 * 4];
            int gc = gcol0 + c4 * 4;
            if (MODE == 1) {
                v.x += bias[gc + 0]; v.y += bias[gc + 1];
                v.z += bias[gc + 2]; v.w += bias[gc + 3];
                v.x = fmaxf(v.x, 0.f); v.y = fmaxf(v.y, 0.f);
                v.z = fmaxf(v.z, 0.f); v.w = fmaxf(v.w, 0.f);
                *(float4*)(O0 + (size_t)grow * 256 + gc) = v;
            } else {
                if (gc < 128) {
                    *(float4*)(O0 + (size_t)grow * 128 + gc) = v;
                } else {
                    int c = gc - 128;
                    v.x += bias[c + 0]; v.y += bias[c + 1];
                    v.z += bias[c + 2]; v.w += bias[c + 3];
                    *(float4*)(O1 + (size_t)grow * 128 + c) = v;
                }
            }
        }
    }
}

// wrappers binding scratch symbols on the device side
__global__ __launch_bounds__(256) void gemm1_k(
    const float* __restrict__ x, const float* __restrict__ W1l,
    const float* __restrict__ W1r, const float* __restrict__ b1)
{
    wmma_gemm_body<1>(g_z, x, D_IN, D_IN, W1l, W1r, b1, g_h, nullptr);
}

__global__ __launch_bounds__(256) void gemm2_k(
    const float* __restrict__ W2l, const float* __restrict__ W2r,
    const float* __restrict__ b2, float* __restrict__ out)
{
    wmma_gemm_body<2>(g_h, g_h + 128, D_HID, D_HID, W2l, W2r, b2, g_z, out);
}

// ---------------- launch ----------------
extern "C" void kernel_launch(void* const* d_in, const int* in_sizes, int n_in,
                              void* d_out, int out_size) {
    const float* x   = (const float*)d_in[0];
    const void*  ei  = d_in[1];                 // int32 or int64; detected at runtime
    const float* W1l = (const float*)d_in[2];
    const float* b1  = (const float*)d_in[3];
    const float* W1r = (const float*)d_in[4];
    const float* W2l = (const float*)d_in[5];
    const float* b2  = (const float*)d_in[6];
    const float* W2r = (const float*)d_in[7];
    float*       out = (float*)d_out;

    // CSR build (per launch; deterministic)
    zero_cnt_k<<<(N_NODES + 255) / 256, 256>>>((const int*)ei);
    count_k<<<(N_EDGES + 255) / 256, 256>>>(ei);
    scan_a_k<<<NBLK, 1024>>>();
    scan_c_k<<<NBLK, 1024>>>();
    place_k<<<(N_EDGES + 255) / 256, 256>>>(ei);

    const int gather_blocks = (N_NODES * 32 + 255) / 256;
    const dim3 gg(256 / 64, (N_NODES + 127) / 128);   // 4 x 391

    // Layer 1: g_z = mean_agg(x) ; g_h = relu([g_z|x]@[W1l;W1r] + b1)
    gather_x_to_z_k<<<gather_blocks, 256>>>(x);
    gemm1_k<<<gg, 256>>>(x, W1l, W1r, b1);

    // Layer 2: [g_z | out] = g_h@[W2l | W2r] (+b2 on out) ; out += mean_agg(g_z)
    gemm2_k<<<gg, 256>>>(W2l, W2r, b2, out);
    gather_z_add_out_k<<<gather_blocks, 256>>>(out);
}